// round 15
// baseline (speedup 1.0000x reference)
#include <cuda_runtime.h>
#include <cuda_bf16.h>
#include <cstdint>

#define N_IMG 64
#define IMG_ELEMS (3 * 512 * 512)          // 786432
#define BINS 256

#define THREADS 384                         // 12 warps
#define NWARP   (THREADS / 32)              // 12
#define CHUNK   49152                       // 128 elems/thread -> u8 counts safe
#define CPI     (IMG_ELEMS / CHUNK)         // 16 sibling blocks per image
#define NBLOCKS (N_IMG * CPI)               // 1024
#define ITERS   (CHUNK / 4 / THREADS)       // 32 float4 iters (= idx regs/thread)
#define H_WORDS (THREADS * BINS / 4)        // 24576 u32 = 96 KB private hists
#define DYN_SMEM (H_WORDS * 4)              // 98304 B -> 2 blocks/SM (192 KB)
#define RGROUPS (NWARP / 2)                 // 6 reduce groups (2 regions each)

// ---------------- global coordination state (all zero-init = identity) --------
// min slot stores ~fenc(min) under atomicMax; max slot stores fenc(max) under
// atomicMax. Zero is the identity for both -> no init kernel; the last-arriving
// block per image resets everything to zero for the next graph replay.
__device__ unsigned int g_minmax[2 * N_IMG];
__device__ int g_hist[N_IMG * BINS];
__device__ int g_cnt1[N_IMG];                  // minmax arrivals
__device__ int g_cnt2[N_IMG];                  // hist arrivals
__device__ int g_cnt3[N_IMG];                  // completion arrivals (reset owner)

__device__ __forceinline__ unsigned fenc(float f) {
    unsigned u = __float_as_uint(f);
    return (u & 0x80000000u) ? ~u : (u | 0x80000000u);
}
__device__ __forceinline__ float fdec(unsigned u) {
    u = (u & 0x80000000u) ? (u ^ 0x80000000u) : ~u;
    return __uint_as_float(u);
}

// ---------------- fused equalize: minmax -> hist -> cdf -> gather -> reset ----
__global__ void __launch_bounds__(THREADS, 2)
k_equalize(const float4* __restrict__ x, float4* __restrict__ out) {
    extern __shared__ uint32_t shw[];               // 96 KB private hists, then lut
    unsigned char* sh = reinterpret_cast<unsigned char*>(shw);
    float* lutf = reinterpret_cast<float*>(shw);

    int b = blockIdx.x, t = threadIdx.x;
    int img = b / CPI;
    int base4 = b * (CHUNK / 4);
    unsigned lane = t & 31u;
    unsigned wreg = (unsigned)(t >> 5);              // 0..11
    unsigned cbase = wreg * 8192u + lane * 4u;       // bank == lane hist column

    __shared__ float smn[NWARP], smx[NWARP];
    __shared__ int slast;

    // ---- P1: block minmax over my chunk (serial accumulator - proven best) ---
    float mn = 3.4e38f, mx = -3.4e38f;
#pragma unroll 8
    for (int i = 0; i < ITERS; i++) {
        float4 v = x[base4 + i * THREADS + t];
        mn = fminf(mn, fminf(fminf(v.x, v.y), fminf(v.z, v.w)));
        mx = fmaxf(mx, fmaxf(fmaxf(v.x, v.y), fmaxf(v.z, v.w)));
    }
#pragma unroll
    for (int o = 16; o > 0; o >>= 1) {
        mn = fminf(mn, __shfl_xor_sync(0xffffffffu, mn, o));
        mx = fmaxf(mx, __shfl_xor_sync(0xffffffffu, mx, o));
    }
    if (lane == 0) { smn[wreg] = mn; smx[wreg] = mx; }
    __syncthreads();
    if (t == 0) {
#pragma unroll
        for (int i = 1; i < NWARP; i++) {
            mn = fminf(mn, smn[i]);
            mx = fmaxf(mx, smx[i]);
        }
        atomicMax(&g_minmax[img], ~fenc(mn));          // zero-identity min
        atomicMax(&g_minmax[N_IMG + img], fenc(mx));   // zero-identity max
        __threadfence();
        atomicAdd(&g_cnt1[img], 1);
    }
    // zero private hists while waiting (overlaps the barrier)
    uint4* shv = reinterpret_cast<uint4*>(shw);
#pragma unroll
    for (int i = 0; i < H_WORDS / 4 / THREADS; i++)
        shv[t + i * THREADS] = make_uint4(0, 0, 0, 0);
    if (t == 0) {
        while (*((volatile int*)&g_cnt1[img]) < CPI) __nanosleep(64);
        __threadfence();
    }
    __syncthreads();

    float gmn = fdec(~__ldcg(&g_minmax[img]));
    float gmx = fdec(__ldcg(&g_minmax[N_IMG + img]));
    float inv = 1.0f / (gmx - gmn + 1e-8f);

    // ---- P2: bucket (L2-hot re-read), idx -> registers, bank==lane hists ----
    uint32_t idxr[ITERS];
#pragma unroll
    for (int i = 0; i < ITERS; i++) {
        float4 v = __ldcs(&x[base4 + i * THREADS + t]);   // last read: evict
        unsigned b0 = (unsigned)(int)fminf(fmaxf((v.x - gmn) * 255.0f * inv, 0.0f), 255.0f);
        unsigned b1 = (unsigned)(int)fminf(fmaxf((v.y - gmn) * 255.0f * inv, 0.0f), 255.0f);
        unsigned b2 = (unsigned)(int)fminf(fmaxf((v.z - gmn) * 255.0f * inv, 0.0f), 255.0f);
        unsigned b3 = (unsigned)(int)fminf(fmaxf((v.w - gmn) * 255.0f * inv, 0.0f), 255.0f);
        idxr[i] = b0 | (b1 << 8) | (b2 << 16) | (b3 << 24);
        sh[cbase + (b0 >> 2) * 128u + (b0 & 3u)]++;
        sh[cbase + (b1 >> 2) * 128u + (b1 & 3u)]++;
        sh[cbase + (b2 >> 2) * 128u + (b2 & 3u)]++;
        sh[cbase + (b3 >> 2) * 128u + (b3 & 3u)]++;
    }
    __syncthreads();

    // ---- P3: reduce private hists -> g_hist (lane-staggered, conflict-free) --
    // thread (q = t&63, g = t>>6, g in 0..5): quad q over warp-regions {2g,2g+1}
    {
        int q = t & 63, g = t >> 6;
        uint32_t s02 = 0, s13 = 0;
#pragma unroll
        for (int r = 0; r < 2; r++) {
            int w2 = g * 2 + r;
#pragma unroll 8
            for (int i = 0; i < 32; i++) {
                int l = (i + t) & 31;
                uint32_t v = shw[w2 * 2048 + q * 32 + l];
                s02 += v & 0x00FF00FFu;
                s13 += (v >> 8) & 0x00FF00FFu;
            }
        }
        __syncthreads();
        shw[t * 2] = s02;
        shw[t * 2 + 1] = s13;
        __syncthreads();
        if (t < 64) {
            uint32_t a02 = 0, a13 = 0;
#pragma unroll
            for (int k = 0; k < RGROUPS; k++) {
                a02 += shw[(k * 64 + t) * 2];
                a13 += shw[(k * 64 + t) * 2 + 1];
            }
            // max 6 * 8192 = 49152 per packed half: no cross-half carry
            int base = img * BINS + t * 4;
            atomicAdd(&g_hist[base + 0], (int)(a02 & 0xFFFFu));
            atomicAdd(&g_hist[base + 1], (int)(a13 & 0xFFFFu));
            atomicAdd(&g_hist[base + 2], (int)(a02 >> 16));
            atomicAdd(&g_hist[base + 3], (int)(a13 >> 16));
        }
        __syncthreads();
        if (t == 0) {
            __threadfence();
            atomicAdd(&g_cnt2[img], 1);
            while (*((volatile int*)&g_cnt2[img]) < CPI) __nanosleep(64);
            __threadfence();
        }
        __syncthreads();
    }

    // ---- P4a: warp 0 scans the 256-bin cdf, LUT into smem ----
    if (t < 32) {
        int loc[8];
        int s = 0;
#pragma unroll
        for (int j = 0; j < 8; j++) {
            s += __ldcg(&g_hist[img * BINS + t * 8 + j]);
            loc[j] = s;                                    // inclusive within lane
        }
        int sc = s;
#pragma unroll
        for (int o = 1; o < 32; o <<= 1) {
            int n = __shfl_up_sync(0xffffffffu, sc, (unsigned)o);
            if (t >= o) sc += n;
        }
        int excl = sc - s;
        float c0   = (float)__shfl_sync(0xffffffffu, loc[0], 0);  // cdf[0]
        float ctot = (float)__shfl_sync(0xffffffffu, sc, 31);     // cdf[255]
        float dinv = 1.0f / (ctot - c0 + 1e-8f);
#pragma unroll
        for (int j = 0; j < 8; j++)
            lutf[t * 8 + j] = ((float)(excl + loc[j]) - c0) * dinv;
    }
    __syncthreads();     // g_hist fully consumed into lutf after this point

    // ---- P4b: gather from register idx, stream out ----
#pragma unroll
    for (int i = 0; i < ITERS; i++) {
        uint32_t u = idxr[i];
        float4 r;
        r.x = lutf[u & 0xFFu];
        r.y = lutf[(u >> 8) & 0xFFu];
        r.z = lutf[(u >> 16) & 0xFFu];
        r.w = lutf[u >> 24];
        __stcs(&out[base4 + i * THREADS + t], r);
    }

    // ---- epilogue: last-arriving sibling resets this image's state ----------
    if (t == 0)
        slast = (atomicAdd(&g_cnt3[img], 1) == CPI - 1) ? 1 : 0;
    __syncthreads();
    if (slast) {
        if (t < BINS / 4) {
            int4* h4 = reinterpret_cast<int4*>(&g_hist[img * BINS]);
            h4[t] = make_int4(0, 0, 0, 0);
        }
        if (t == 64) g_minmax[img] = 0u;
        if (t == 65) g_minmax[N_IMG + img] = 0u;
        if (t == 66) g_cnt1[img] = 0;
        if (t == 67) g_cnt2[img] = 0;
        if (t == 68) g_cnt3[img] = 0;
    }
}

// ---------------- launch -------------------------------------------------------
extern "C" void kernel_launch(void* const* d_in, const int* in_sizes, int n_in,
                              void* d_out, int out_size) {
    const float4* x = reinterpret_cast<const float4*>(d_in[0]);
    float4* out = reinterpret_cast<float4*>(d_out);

    static bool configured = false;
    if (!configured) {
        cudaFuncSetAttribute(k_equalize,
                             cudaFuncAttributeMaxDynamicSharedMemorySize, DYN_SMEM);
        configured = true;
    }
    k_equalize<<<NBLOCKS, THREADS, DYN_SMEM>>>(x, out);
}

// round 16
// speedup vs baseline: 1.3747x; 1.3747x over previous
#include <cuda_runtime.h>
#include <cuda_bf16.h>
#include <cstdint>

#define N_IMG 64
#define IMG_ELEMS (3 * 512 * 512)          // 786432
#define BINS 256

#define THREADS 256                         // 8 warps  (R13 optimum)
#define CHUNK   32768                       // 128 elems/thread -> u8 counts safe
#define CPI     (IMG_ELEMS / CHUNK)         // 24 sibling blocks per image
#define NBLOCKS (N_IMG * CPI)               // 1536
#define ITERS   (CHUNK / 4 / THREADS)       // 32 float4 iters (= idx regs/thread)
#define H_WORDS (THREADS * BINS / 4)        // 16384 u32 = 64 KB private hists
#define DYN_SMEM (H_WORDS * 4)              // 65536 B -> 3 blocks/SM

// ---------------- global coordination state (all zero-init = identity) --------
__device__ unsigned int g_minmax[2 * N_IMG];
__device__ int g_hist[N_IMG * BINS];
__device__ int g_cnt1[N_IMG];                  // minmax arrivals
__device__ int g_cnt2[N_IMG];                  // hist arrivals
__device__ int g_cnt3[N_IMG];                  // completion arrivals (reset owner)

__device__ __forceinline__ unsigned fenc(float f) {
    unsigned u = __float_as_uint(f);
    return (u & 0x80000000u) ? ~u : (u | 0x80000000u);
}
__device__ __forceinline__ float fdec(unsigned u) {
    u = (u & 0x80000000u) ? (u ^ 0x80000000u) : ~u;
    return __uint_as_float(u);
}
// release-publish +1 (orders all prior writes incl. atomics before the add)
__device__ __forceinline__ void pub_add(int* p) {
    asm volatile("red.release.gpu.global.add.s32 [%0], 1;" :: "l"(p) : "memory");
}
// acquire poll
__device__ __forceinline__ int ld_acq(const int* p) {
    int v;
    asm volatile("ld.acquire.gpu.global.s32 %0, [%1];" : "=r"(v) : "l"(p) : "memory");
    return v;
}
// acq_rel fetch-add (epilogue election)
__device__ __forceinline__ int add_acqrel(int* p) {
    int v;
    asm volatile("atom.acq_rel.gpu.global.add.s32 %0, [%1], 1;" : "=r"(v) : "l"(p) : "memory");
    return v;
}

// ---------------- fused equalize: minmax -> hist -> cdf -> gather -> reset ----
__global__ void __launch_bounds__(THREADS, 3)
k_equalize(const float4* __restrict__ x, float4* __restrict__ out) {
    extern __shared__ uint32_t shw[];               // 64 KB private hists, then lut
    unsigned char* sh = reinterpret_cast<unsigned char*>(shw);
    float* lutf = reinterpret_cast<float*>(shw);

    int b = blockIdx.x, t = threadIdx.x;
    int img = b / CPI;
    int base4 = b * (CHUNK / 4);
    unsigned lane = t & 31u;
    unsigned wreg = (unsigned)(t >> 5);              // 0..7
    unsigned cbase = wreg * 8192u + lane * 4u;       // bank == lane hist column

    __shared__ float smn[8], smx[8];
    __shared__ int slast;

    // ---- P1: block minmax over my chunk (serial accumulator - proven best) ---
    float mn = 3.4e38f, mx = -3.4e38f;
#pragma unroll 8
    for (int i = 0; i < ITERS; i++) {
        float4 v = x[base4 + i * THREADS + t];
        mn = fminf(mn, fminf(fminf(v.x, v.y), fminf(v.z, v.w)));
        mx = fmaxf(mx, fmaxf(fmaxf(v.x, v.y), fmaxf(v.z, v.w)));
    }
#pragma unroll
    for (int o = 16; o > 0; o >>= 1) {
        mn = fminf(mn, __shfl_xor_sync(0xffffffffu, mn, o));
        mx = fmaxf(mx, __shfl_xor_sync(0xffffffffu, mx, o));
    }
    if (lane == 0) { smn[wreg] = mn; smx[wreg] = mx; }
    __syncthreads();
    if (t == 0) {
#pragma unroll
        for (int i = 1; i < 8; i++) {
            mn = fminf(mn, smn[i]);
            mx = fmaxf(mx, smx[i]);
        }
        atomicMax(&g_minmax[img], ~fenc(mn));          // zero-identity min
        atomicMax(&g_minmax[N_IMG + img], fenc(mx));   // zero-identity max
        pub_add(&g_cnt1[img]);                         // release-publish
    }
    // zero private hists while waiting (overlaps the barrier)
    uint4* shv = reinterpret_cast<uint4*>(shw);
#pragma unroll
    for (int i = 0; i < H_WORDS / 4 / THREADS; i++)
        shv[t + i * THREADS] = make_uint4(0, 0, 0, 0);
    if (t == 0) {
        while (ld_acq(&g_cnt1[img]) < CPI) __nanosleep(32);
    }
    __syncthreads();

    float gmn = fdec(~__ldcg(&g_minmax[img]));
    float gmx = fdec(__ldcg(&g_minmax[N_IMG + img]));
    float inv = 1.0f / (gmx - gmn + 1e-8f);
    float sb = 255.0f * inv;                 // bin = clamp(v*sb + ob): single FFMA
    float ob = -gmn * sb;

    // ---- P2: bucket (L2-hot re-read), idx -> registers, bank==lane hists ----
    uint32_t idxr[ITERS];
#pragma unroll
    for (int i = 0; i < ITERS; i++) {
        float4 v = __ldcs(&x[base4 + i * THREADS + t]);   // last read: evict
        unsigned b0 = (unsigned)(int)fminf(fmaxf(fmaf(v.x, sb, ob), 0.0f), 255.0f);
        unsigned b1 = (unsigned)(int)fminf(fmaxf(fmaf(v.y, sb, ob), 0.0f), 255.0f);
        unsigned b2 = (unsigned)(int)fminf(fmaxf(fmaf(v.z, sb, ob), 0.0f), 255.0f);
        unsigned b3 = (unsigned)(int)fminf(fmaxf(fmaf(v.w, sb, ob), 0.0f), 255.0f);
        idxr[i] = b0 | (b1 << 8) | (b2 << 16) | (b3 << 24);
        sh[cbase + (b0 >> 2) * 128u + (b0 & 3u)]++;
        sh[cbase + (b1 >> 2) * 128u + (b1 & 3u)]++;
        sh[cbase + (b2 >> 2) * 128u + (b2 & 3u)]++;
        sh[cbase + (b3 >> 2) * 128u + (b3 & 3u)]++;
    }
    __syncthreads();

    // ---- P3: reduce private hists -> g_hist (lane-staggered, conflict-free) --
    {
        int q = t & 63, g = t >> 6;                       // g in 0..3
        uint32_t s02 = 0, s13 = 0;
#pragma unroll
        for (int r = 0; r < 2; r++) {
            int w2 = g * 2 + r;
#pragma unroll 8
            for (int i = 0; i < 32; i++) {
                int l = (i + t) & 31;
                uint32_t v = shw[w2 * 2048 + q * 32 + l];
                s02 += v & 0x00FF00FFu;
                s13 += (v >> 8) & 0x00FF00FFu;
            }
        }
        __syncthreads();
        shw[t * 2] = s02;
        shw[t * 2 + 1] = s13;
        __syncthreads();
        if (t < 64) {
            uint32_t a02 = shw[t * 2]             + shw[(64 + t) * 2]
                         + shw[(128 + t) * 2]     + shw[(192 + t) * 2];
            uint32_t a13 = shw[t * 2 + 1]         + shw[(64 + t) * 2 + 1]
                         + shw[(128 + t) * 2 + 1] + shw[(192 + t) * 2 + 1];
            // max 4 * 8192 = 32768 per packed half: no cross-half carry
            int base = img * BINS + t * 4;
            atomicAdd(&g_hist[base + 0], (int)(a02 & 0xFFFFu));
            atomicAdd(&g_hist[base + 1], (int)(a13 & 0xFFFFu));
            atomicAdd(&g_hist[base + 2], (int)(a02 >> 16));
            atomicAdd(&g_hist[base + 3], (int)(a13 >> 16));
        }
        __syncthreads();
        if (t == 0) {
            pub_add(&g_cnt2[img]);                        // release-publish
            while (ld_acq(&g_cnt2[img]) < CPI) __nanosleep(32);
        }
        __syncthreads();
    }

    // ---- P4a: warp 0 scans the 256-bin cdf, LUT into smem ----
    if (t < 32) {
        int loc[8];
        int s = 0;
#pragma unroll
        for (int j = 0; j < 8; j++) {
            s += __ldcg(&g_hist[img * BINS + t * 8 + j]);
            loc[j] = s;                                    // inclusive within lane
        }
        int sc = s;
#pragma unroll
        for (int o = 1; o < 32; o <<= 1) {
            int n = __shfl_up_sync(0xffffffffu, sc, (unsigned)o);
            if (t >= o) sc += n;
        }
        int excl = sc - s;
        float c0   = (float)__shfl_sync(0xffffffffu, loc[0], 0);  // cdf[0]
        float ctot = (float)__shfl_sync(0xffffffffu, sc, 31);     // cdf[255]
        float dinv = 1.0f / (ctot - c0 + 1e-8f);
#pragma unroll
        for (int j = 0; j < 8; j++)
            lutf[t * 8 + j] = ((float)(excl + loc[j]) - c0) * dinv;
    }
    __syncthreads();     // g_hist fully consumed into lutf after this point

    // ---- P4b: gather from register idx, stream out ----
#pragma unroll
    for (int i = 0; i < ITERS; i++) {
        uint32_t u = idxr[i];
        float4 r;
        r.x = lutf[u & 0xFFu];
        r.y = lutf[(u >> 8) & 0xFFu];
        r.z = lutf[(u >> 16) & 0xFFu];
        r.w = lutf[u >> 24];
        __stcs(&out[base4 + i * THREADS + t], r);
    }

    // ---- epilogue: last-arriving sibling resets this image's state ----------
    if (t == 0)
        slast = (add_acqrel(&g_cnt3[img]) == CPI - 1) ? 1 : 0;
    __syncthreads();
    if (slast) {
        if (t < BINS / 4) {
            int4* h4 = reinterpret_cast<int4*>(&g_hist[img * BINS]);
            h4[t] = make_int4(0, 0, 0, 0);
        }
        if (t == 64) g_minmax[img] = 0u;
        if (t == 65) g_minmax[N_IMG + img] = 0u;
        if (t == 66) g_cnt1[img] = 0;
        if (t == 67) g_cnt2[img] = 0;
        if (t == 68) g_cnt3[img] = 0;
    }
}

// ---------------- launch -------------------------------------------------------
extern "C" void kernel_launch(void* const* d_in, const int* in_sizes, int n_in,
                              void* d_out, int out_size) {
    const float4* x = reinterpret_cast<const float4*>(d_in[0]);
    float4* out = reinterpret_cast<float4*>(d_out);

    static bool configured = false;
    if (!configured) {
        cudaFuncSetAttribute(k_equalize,
                             cudaFuncAttributeMaxDynamicSharedMemorySize, DYN_SMEM);
        configured = true;
    }
    k_equalize<<<NBLOCKS, THREADS, DYN_SMEM>>>(x, out);
}